// round 9
// baseline (speedup 1.0000x reference)
#include <cuda_runtime.h>
#include <math.h>

// Problem constants (fixed shapes for this problem)
#define SL     32          // B*C slices
#define NP     50          // projections
#define NTASK  (SL * NP)   // 1600 (slice, projection) tasks
#define NELEM  32768       // samples per slice
#define NB     2048        // histogram bins (one u32 word per bin: X lo16, Y hi16)
#define RSCALE 128.0f      // NB / 16  (range [-8, 8])
#define BIASF  1024.0f     // NB / 2
#define BINW   (1.0f/128.0f)
#define TPB    128
#define BPSM   16
#define GRID   (148 * BPSM)   // 2368: 16 resident blocks x 148 SMs

__device__ float g_w2[NTASK];
__device__ unsigned int g_task = 0;
__device__ unsigned int g_done = 0;

__device__ __forceinline__ int cumX(const unsigned int* h, int b) { return (int)(h[b] & 0xffffu); }
__device__ __forceinline__ int cumY(const unsigned int* h, int b) { return (int)(h[b] >> 16); }

// Float-domain bin: clamp on the fma pipe (FMNMX), single F2I at the end.
__device__ __forceinline__ int fbin(float vx, float vy, float a0, float a1) {
    float v = fmaf(vx, a0, fmaf(vy, a1, BIASF));
    v = fminf(fmaxf(v, 0.0f), (float)(NB - 1));
    return (int)v;
}

// In-place exclusive SIMD scan of packed (X lo16 | Y hi16) histogram, NB words.
// 128 threads x 16 words. Each half's cum <= 32768 = 0x8000: lo16 never carries.
__device__ __forceinline__ void scan_packed(unsigned int* h, unsigned int* wsum, int t) {
    const int base = t * 16;
    unsigned int v[16];
#pragma unroll
    for (int k = 0; k < 16; k++) v[k] = h[base + k];
    unsigned int s = 0;
#pragma unroll
    for (int k = 0; k < 16; k++) { unsigned int tmp = v[k]; v[k] = s; s += tmp; }

    const int lane = t & 31, wid = t >> 5;
    unsigned int inc = s;
#pragma unroll
    for (int d = 1; d < 32; d <<= 1) {
        unsigned int y = __shfl_up_sync(0xffffffffu, inc, d);
        if (lane >= d) inc += y;
    }
    if (lane == 31) wsum[wid] = inc;
    const unsigned int excl = inc - s;
    __syncthreads();
    if (t == 0) {
        unsigned int s2 = 0;
#pragma unroll
        for (int j = 0; j < 4; j++) { unsigned int tmp = wsum[j]; wsum[j] = s2; s2 += tmp; }
    }
    __syncthreads();
    const unsigned int off = excl + wsum[wid];
#pragma unroll
    for (int k = 0; k < 16; k++) h[base + k] = v[k] + off;
    __syncthreads();
}

// Merge step-quantile functions over this thread's rank range.
__device__ __forceinline__ float merge_ranks(const unsigned int* h, int t) {
    const int perT = NELEM / TPB;          // 256
    const int r0 = t * perT;
    const int r1 = r0 + perT;

    int bx = 0, by = 0;
#pragma unroll
    for (int step = NB / 2; step > 0; step >>= 1)
        if (cumX(h, bx + step) <= r0) bx += step;
#pragma unroll
    for (int step = NB / 2; step > 0; step >>= 1)
        if (cumY(h, by + step) <= r0) by += step;

    float acc = 0.0f;
    int r = r0;
    while (r < r1) {
        int nx = cumX(h, bx + 1);
        int ny = cumY(h, by + 1);
        int nb = min(min(nx, ny), r1);
        float d = (float)(bx - by) * BINW;
        acc += (float)(nb - r) * d * d;
        r = nb;
        if (r >= r1) break;
        while (cumX(h, bx + 1) <= r) ++bx;
        while (cumY(h, by + 1) <= r) ++by;
    }
    return acc;
}

__global__ __launch_bounds__(TPB, BPSM)
void hist_w2_kernel(const float* __restrict__ X,
                    const float* __restrict__ Y,
                    const float* __restrict__ PR,
                    float* __restrict__ out) {
    __shared__ unsigned int h[NB + 1];
    __shared__ unsigned int wsum[4];
    __shared__ double dsum[4];
    __shared__ unsigned int s_task;

    const int t = threadIdx.x;

    for (;;) {
        // Dynamic task fetch: placement-independent load balance.
        if (t == 0) s_task = atomicAdd(&g_task, 1u);
        __syncthreads();
        const int task = (int)s_task;
        if (task >= NTASK) break;

        const int sl = task / NP;
        const int p  = task - sl * NP;

        const float a0 = PR[2 * p]     * RSCALE;
        const float a1 = PR[2 * p + 1] * RSCALE;

        for (int i = t; i < NB + 1; i += TPB) h[i] = 0u;
        __syncthreads();

        const float4* xs = (const float4*)X + (size_t)sl * (NELEM / 2);
        const float4* ys = (const float4*)Y + (size_t)sl * (NELEM / 2);

        // Histogram pass: 2x unrolled -> 4 independent LDG.128 per iter (MLP=4),
        // one atomic lane per (point, projection).
        for (int i = t; i < NELEM / 2; i += 2 * TPB) {
            float4 xv0 = xs[i];
            float4 xv1 = xs[i + TPB];
            float4 yv0 = ys[i];
            float4 yv1 = ys[i + TPB];

            int xa = fbin(xv0.x, xv0.y, a0, a1);
            int xb = fbin(xv0.z, xv0.w, a0, a1);
            int xc = fbin(xv1.x, xv1.y, a0, a1);
            int xd = fbin(xv1.z, xv1.w, a0, a1);
            int ya = fbin(yv0.x, yv0.y, a0, a1);
            int yb = fbin(yv0.z, yv0.w, a0, a1);
            int yc = fbin(yv1.x, yv1.y, a0, a1);
            int yd = fbin(yv1.z, yv1.w, a0, a1);

            atomicAdd(&h[xa], 1u);
            atomicAdd(&h[xb], 1u);
            atomicAdd(&h[xc], 1u);
            atomicAdd(&h[xd], 1u);
            atomicAdd(&h[ya], 0x10000u);
            atomicAdd(&h[yb], 0x10000u);
            atomicAdd(&h[yc], 0x10000u);
            atomicAdd(&h[yd], 0x10000u);
        }
        __syncthreads();

        scan_packed(h, wsum, t);
        if (t == 0) h[NB] = 0x80008000u;
        __syncthreads();

        float acc = merge_ranks(h, t);

        // Block reduction in double.
        double da = (double)acc;
        const int lane = t & 31, wid = t >> 5;
#pragma unroll
        for (int d = 16; d > 0; d >>= 1) da += __shfl_down_sync(0xffffffffu, da, d);
        if (lane == 0) dsum[wid] = da;
        __syncthreads();
        if (t == 0) {
            double tot = 0.0;
#pragma unroll
            for (int j = 0; j < 4; j++) tot += dsum[j];
            g_w2[task] = (float)(tot * (1.0 / (double)NELEM));
        }
        __syncthreads();   // protects s_task/h reuse next iteration
    }

    // Last-block-does-finalize (single launch; graph-replay safe via reset).
    __threadfence();
    __shared__ unsigned int s_rank;
    if (t == 0) s_rank = atomicAdd(&g_done, 1u);
    __syncthreads();
    if (s_rank == GRID - 1) {
        __threadfence();  // acquire: make all g_w2 writes visible
        float sw = 0.0f;
        if (t < SL) {
            float s = 0.0f;
#pragma unroll 10
            for (int p = 0; p < NP; p++) s += g_w2[t * NP + p];
            sw = sqrtf(s * (1.0f / (float)NP));
        }
        if (t < 32) {
#pragma unroll
            for (int d = 16; d > 0; d >>= 1) sw += __shfl_down_sync(0xffffffffu, sw, d);
            if (t == 0) {
                out[0] = sw * (1.0f / (float)SL);
                g_task = 0;  // reset counters for next graph replay
                g_done = 0;
            }
        }
    }
}

extern "C" void kernel_launch(void* const* d_in, const int* in_sizes, int n_in,
                              void* d_out, int out_size) {
    // Identify projections by element count (100); the other two are the point
    // sets (W2 between order statistics is symmetric in X/Y, order irrelevant).
    const float* X = nullptr;
    const float* Y = nullptr;
    const float* PR = nullptr;
    for (int i = 0; i < n_in; i++) {
        if (in_sizes[i] == NP * 2) {
            PR = (const float*)d_in[i];
        } else if (!X) {
            X = (const float*)d_in[i];
        } else {
            Y = (const float*)d_in[i];
        }
    }
    hist_w2_kernel<<<GRID, TPB>>>(X, Y, PR, (float*)d_out);
}

// round 10
// speedup vs baseline: 1.1004x; 1.1004x over previous
#include <cuda_runtime.h>
#include <math.h>

// Problem constants (fixed shapes for this problem)
#define SL     32          // B*C slices
#define NP     50          // projections
#define NTASK  (SL * NP)   // 1600 (slice, projection) tasks
#define NELEM  32768       // samples per slice
#define NB     2048        // histogram bins (one u32 word per bin: X lo16, Y hi16)
#define RSCALE 128.0f      // NB / 16  (range [-8, 8])
#define BIASF  1024.0f     // NB / 2
#define BINW   (1.0f/128.0f)
#define TPB    512
#define BPSM   4
#define GRID   (148 * BPSM)   // 592: 4 resident blocks x 148 SMs, ~2.7 tasks/block

__device__ float g_w2[NTASK];
__device__ unsigned int g_task = 0;
__device__ unsigned int g_done = 0;

__device__ __forceinline__ int cumX(const unsigned int* h, int b) { return (int)(h[b] & 0xffffu); }
__device__ __forceinline__ int cumY(const unsigned int* h, int b) { return (int)(h[b] >> 16); }

// Float-domain bin: clamp on the fma pipe (FMNMX), single F2I at the end.
__device__ __forceinline__ int fbin(float vx, float vy, float a0, float a1) {
    float v = fmaf(vx, a0, fmaf(vy, a1, BIASF));
    v = fminf(fmaxf(v, 0.0f), (float)(NB - 1));
    return (int)v;
}

// In-place exclusive SIMD scan of packed (X lo16 | Y hi16) histogram, NB words.
// 512 threads x 4 words. Each half's cum <= 32768 = 0x8000: lo16 never carries.
__device__ __forceinline__ void scan_packed(unsigned int* h, unsigned int* wsum, int t) {
    const int base = t * 4;
    unsigned int v[4];
#pragma unroll
    for (int k = 0; k < 4; k++) v[k] = h[base + k];
    unsigned int s = 0;
#pragma unroll
    for (int k = 0; k < 4; k++) { unsigned int tmp = v[k]; v[k] = s; s += tmp; }

    const int lane = t & 31, wid = t >> 5;   // 16 warps
    unsigned int inc = s;
#pragma unroll
    for (int d = 1; d < 32; d <<= 1) {
        unsigned int y = __shfl_up_sync(0xffffffffu, inc, d);
        if (lane >= d) inc += y;
    }
    if (lane == 31) wsum[wid] = inc;
    const unsigned int excl = inc - s;
    __syncthreads();
    if (t == 0) {
        unsigned int s2 = 0;
#pragma unroll
        for (int j = 0; j < 16; j++) { unsigned int tmp = wsum[j]; wsum[j] = s2; s2 += tmp; }
    }
    __syncthreads();
    const unsigned int off = excl + wsum[wid];
#pragma unroll
    for (int k = 0; k < 4; k++) h[base + k] = v[k] + off;
    __syncthreads();
}

// Merge step-quantile functions over this thread's rank range.
__device__ __forceinline__ float merge_ranks(const unsigned int* h, int t) {
    const int perT = NELEM / TPB;          // 64
    const int r0 = t * perT;
    const int r1 = r0 + perT;

    int bx = 0, by = 0;
#pragma unroll
    for (int step = NB / 2; step > 0; step >>= 1)
        if (cumX(h, bx + step) <= r0) bx += step;
#pragma unroll
    for (int step = NB / 2; step > 0; step >>= 1)
        if (cumY(h, by + step) <= r0) by += step;

    float acc = 0.0f;
    int r = r0;
    while (r < r1) {
        int nx = cumX(h, bx + 1);
        int ny = cumY(h, by + 1);
        int nb = min(min(nx, ny), r1);
        float d = (float)(bx - by) * BINW;
        acc += (float)(nb - r) * d * d;
        r = nb;
        if (r >= r1) break;
        while (cumX(h, bx + 1) <= r) ++bx;
        while (cumY(h, by + 1) <= r) ++by;
    }
    return acc;
}

__global__ __launch_bounds__(TPB, BPSM)
void hist_w2_kernel(const float* __restrict__ X,
                    const float* __restrict__ Y,
                    const float* __restrict__ PR,
                    float* __restrict__ out) {
    __shared__ unsigned int h[NB + 1];
    __shared__ unsigned int wsum[16];
    __shared__ double dsum[16];
    __shared__ unsigned int s_task;

    const int t = threadIdx.x;

    for (;;) {
        // Dynamic task fetch: placement-independent load balance.
        if (t == 0) s_task = atomicAdd(&g_task, 1u);
        __syncthreads();
        const int task = (int)s_task;
        if (task >= NTASK) break;

        const int sl = task / NP;
        const int p  = task - sl * NP;

        const float a0 = PR[2 * p]     * RSCALE;
        const float a1 = PR[2 * p + 1] * RSCALE;

        for (int i = t; i < NB + 1; i += TPB) h[i] = 0u;
        __syncthreads();

        const float4* xs = (const float4*)X + (size_t)sl * (NELEM / 2);
        const float4* ys = (const float4*)Y + (size_t)sl * (NELEM / 2);

        // Histogram pass: 2x unrolled -> 4 independent LDG.128 per iter (MLP=4),
        // one atomic lane per (point, projection).
        for (int i = t; i < NELEM / 2; i += 2 * TPB) {
            float4 xv0 = xs[i];
            float4 xv1 = xs[i + TPB];
            float4 yv0 = ys[i];
            float4 yv1 = ys[i + TPB];

            int xa = fbin(xv0.x, xv0.y, a0, a1);
            int xb = fbin(xv0.z, xv0.w, a0, a1);
            int xc = fbin(xv1.x, xv1.y, a0, a1);
            int xd = fbin(xv1.z, xv1.w, a0, a1);
            int ya = fbin(yv0.x, yv0.y, a0, a1);
            int yb = fbin(yv0.z, yv0.w, a0, a1);
            int yc = fbin(yv1.x, yv1.y, a0, a1);
            int yd = fbin(yv1.z, yv1.w, a0, a1);

            atomicAdd(&h[xa], 1u);
            atomicAdd(&h[xb], 1u);
            atomicAdd(&h[xc], 1u);
            atomicAdd(&h[xd], 1u);
            atomicAdd(&h[ya], 0x10000u);
            atomicAdd(&h[yb], 0x10000u);
            atomicAdd(&h[yc], 0x10000u);
            atomicAdd(&h[yd], 0x10000u);
        }
        __syncthreads();

        scan_packed(h, wsum, t);
        if (t == 0) h[NB] = 0x80008000u;
        __syncthreads();

        float acc = merge_ranks(h, t);

        // Block reduction in double.
        double da = (double)acc;
        const int lane = t & 31, wid = t >> 5;
#pragma unroll
        for (int d = 16; d > 0; d >>= 1) da += __shfl_down_sync(0xffffffffu, da, d);
        if (lane == 0) dsum[wid] = da;
        __syncthreads();
        if (t == 0) {
            double tot = 0.0;
#pragma unroll
            for (int j = 0; j < 16; j++) tot += dsum[j];
            g_w2[task] = (float)(tot * (1.0 / (double)NELEM));
        }
        __syncthreads();   // protects s_task/h reuse next iteration
    }

    // Last-block-does-finalize (single launch; graph-replay safe via reset).
    __threadfence();
    __shared__ unsigned int s_rank;
    if (t == 0) s_rank = atomicAdd(&g_done, 1u);
    __syncthreads();
    if (s_rank == GRID - 1) {
        __threadfence();  // acquire: make all g_w2 writes visible
        float sw = 0.0f;
        if (t < SL) {
            float s = 0.0f;
#pragma unroll 10
            for (int p = 0; p < NP; p++) s += g_w2[t * NP + p];
            sw = sqrtf(s * (1.0f / (float)NP));
        }
        if (t < 32) {
#pragma unroll
            for (int d = 16; d > 0; d >>= 1) sw += __shfl_down_sync(0xffffffffu, sw, d);
            if (t == 0) {
                out[0] = sw * (1.0f / (float)SL);
                g_task = 0;  // reset counters for next graph replay
                g_done = 0;
            }
        }
    }
}

extern "C" void kernel_launch(void* const* d_in, const int* in_sizes, int n_in,
                              void* d_out, int out_size) {
    // Identify projections by element count (100); the other two are the point
    // sets (W2 between order statistics is symmetric in X/Y, order irrelevant).
    const float* X = nullptr;
    const float* Y = nullptr;
    const float* PR = nullptr;
    for (int i = 0; i < n_in; i++) {
        if (in_sizes[i] == NP * 2) {
            PR = (const float*)d_in[i];
        } else if (!X) {
            X = (const float*)d_in[i];
        } else {
            Y = (const float*)d_in[i];
        }
    }
    hist_w2_kernel<<<GRID, TPB>>>(X, Y, PR, (float*)d_out);
}

// round 11
// speedup vs baseline: 1.4511x; 1.3188x over previous
#include <cuda_runtime.h>
#include <math.h>

// Problem constants (fixed shapes for this problem)
#define SL     32          // B*C slices
#define NP     50          // projections
#define NTASK  (SL * NP)   // 1600 (slice, projection) tasks
#define NELEM  32768       // samples per slice
#define NB     1024        // histogram bins
#define NCOPY  8           // bank-replicated copies (lane & 7)
#define RSCALE 64.0f       // NB / 16  (range [-8, 8])
#define BIASF  512.0f      // NB / 2
#define BINW   (1.0f/64.0f)
#define TPB    256
#define BPSM   6
#define GRID   (148 * BPSM)   // 888 blocks; ~1.8 tasks per block slot

__device__ float g_w2[NTASK];
__device__ unsigned int g_task = 0;
__device__ unsigned int g_done = 0;

__device__ __forceinline__ int cumX(const unsigned int* h, int b) { return (int)(h[b] & 0xffffu); }
__device__ __forceinline__ int cumY(const unsigned int* h, int b) { return (int)(h[b] >> 16); }

// Float-domain bin: clamp on the fma pipe (FMNMX), single F2I at the end.
__device__ __forceinline__ int fbin(float vx, float vy, float a0, float a1) {
    float v = fmaf(vx, a0, fmaf(vy, a1, BIASF));
    v = fminf(fmaxf(v, 0.0f), (float)(NB - 1));
    return (int)v;
}

// In-place exclusive SIMD scan of packed (X lo16 | Y hi16) histogram, NB words.
// 256 threads x 4 words. Each half's cum <= 32768 = 0x8000: lo16 never carries.
__device__ __forceinline__ void scan_packed(unsigned int* h, unsigned int* wsum, int t) {
    const int base = t * 4;
    unsigned int v[4];
#pragma unroll
    for (int k = 0; k < 4; k++) v[k] = h[base + k];
    unsigned int s = 0;
#pragma unroll
    for (int k = 0; k < 4; k++) { unsigned int tmp = v[k]; v[k] = s; s += tmp; }

    const int lane = t & 31, wid = t >> 5;   // 8 warps
    unsigned int inc = s;
#pragma unroll
    for (int d = 1; d < 32; d <<= 1) {
        unsigned int y = __shfl_up_sync(0xffffffffu, inc, d);
        if (lane >= d) inc += y;
    }
    if (lane == 31) wsum[wid] = inc;
    const unsigned int excl = inc - s;
    __syncthreads();
    if (t == 0) {
        unsigned int s2 = 0;
#pragma unroll
        for (int j = 0; j < 8; j++) { unsigned int tmp = wsum[j]; wsum[j] = s2; s2 += tmp; }
    }
    __syncthreads();
    const unsigned int off = excl + wsum[wid];
#pragma unroll
    for (int k = 0; k < 4; k++) h[base + k] = v[k] + off;
    __syncthreads();
}

// Merge step-quantile functions over this thread's rank range.
__device__ __forceinline__ float merge_ranks(const unsigned int* h, int t) {
    const int perT = NELEM / TPB;          // 128
    const int r0 = t * perT;
    const int r1 = r0 + perT;

    int bx = 0, by = 0;
#pragma unroll
    for (int step = NB / 2; step > 0; step >>= 1)
        if (cumX(h, bx + step) <= r0) bx += step;
#pragma unroll
    for (int step = NB / 2; step > 0; step >>= 1)
        if (cumY(h, by + step) <= r0) by += step;

    float acc = 0.0f;
    int r = r0;
    while (r < r1) {
        int nx = cumX(h, bx + 1);
        int ny = cumY(h, by + 1);
        int nb = min(min(nx, ny), r1);
        float d = (float)(bx - by) * BINW;
        acc += (float)(nb - r) * d * d;
        r = nb;
        if (r >= r1) break;
        while (cumX(h, bx + 1) <= r) ++bx;
        while (cumY(h, by + 1) <= r) ++by;
    }
    return acc;
}

__global__ __launch_bounds__(TPB, BPSM)
void hist_w2_kernel(const float* __restrict__ X,
                    const float* __restrict__ Y,
                    const float* __restrict__ PR,
                    float* __restrict__ out) {
    // Bank-replicated histogram: word = bin*8 + (lane&7).
    // Lanes with different (lane&7) never share a bank -> atomic replay
    // degree drops from ~3.9 to ~2.4.
    __shared__ unsigned int h8[NB * NCOPY];      // 32 KB
    __shared__ unsigned int h[NB + 1];           // reduced packed CDF table
    __shared__ unsigned int wsum[8];
    __shared__ double dsum[8];
    __shared__ unsigned int s_task;

    const int t = threadIdx.x;
    const int sub = t & (NCOPY - 1);

    for (;;) {
        // Dynamic task fetch: placement-independent load balance.
        if (t == 0) s_task = atomicAdd(&g_task, 1u);
        __syncthreads();
        const int task = (int)s_task;
        if (task >= NTASK) break;

        const int sl = task / NP;
        const int p  = task - sl * NP;

        const float a0 = PR[2 * p]     * RSCALE;
        const float a1 = PR[2 * p + 1] * RSCALE;

        // Zero replicated table (vectorized) + reduced table.
        {
            uint4 z = make_uint4(0u, 0u, 0u, 0u);
            uint4* h8v = (uint4*)h8;
#pragma unroll
            for (int i = t; i < NB * NCOPY / 4; i += TPB) h8v[i] = z;
            for (int i = t; i < NB + 1; i += TPB) h[i] = 0u;
        }
        __syncthreads();

        const float4* xs = (const float4*)X + (size_t)sl * (NELEM / 2);
        const float4* ys = (const float4*)Y + (size_t)sl * (NELEM / 2);

        // Histogram pass: 2x unrolled -> 4 independent LDG.128 per iter (MLP=4),
        // one atomic lane per (point, projection), bank-replicated scatter.
        for (int i = t; i < NELEM / 2; i += 2 * TPB) {
            float4 xv0 = xs[i];
            float4 xv1 = xs[i + TPB];
            float4 yv0 = ys[i];
            float4 yv1 = ys[i + TPB];

            int xa = fbin(xv0.x, xv0.y, a0, a1);
            int xb = fbin(xv0.z, xv0.w, a0, a1);
            int xc = fbin(xv1.x, xv1.y, a0, a1);
            int xd = fbin(xv1.z, xv1.w, a0, a1);
            int ya = fbin(yv0.x, yv0.y, a0, a1);
            int yb = fbin(yv0.z, yv0.w, a0, a1);
            int yc = fbin(yv1.x, yv1.y, a0, a1);
            int yd = fbin(yv1.z, yv1.w, a0, a1);

            atomicAdd(&h8[(xa << 3) | sub], 1u);
            atomicAdd(&h8[(xb << 3) | sub], 1u);
            atomicAdd(&h8[(xc << 3) | sub], 1u);
            atomicAdd(&h8[(xd << 3) | sub], 1u);
            atomicAdd(&h8[(ya << 3) | sub], 0x10000u);
            atomicAdd(&h8[(yb << 3) | sub], 0x10000u);
            atomicAdd(&h8[(yc << 3) | sub], 0x10000u);
            atomicAdd(&h8[(yd << 3) | sub], 0x10000u);
        }
        __syncthreads();

        // Reduce 8 copies -> packed per-bin counts (SIMD u32 add is safe:
        // each 16-bit half total <= 32768).
        {
            const uint4* h8v = (const uint4*)h8;
#pragma unroll
            for (int bin = t; bin < NB; bin += TPB) {
                uint4 a = h8v[bin * 2];
                uint4 b = h8v[bin * 2 + 1];
                h[bin] = a.x + a.y + a.z + a.w + b.x + b.y + b.z + b.w;
            }
        }
        __syncthreads();

        scan_packed(h, wsum, t);
        if (t == 0) h[NB] = 0x80008000u;
        __syncthreads();

        float acc = merge_ranks(h, t);

        // Block reduction in double.
        double da = (double)acc;
        const int lane = t & 31, wid = t >> 5;
#pragma unroll
        for (int d = 16; d > 0; d >>= 1) da += __shfl_down_sync(0xffffffffu, da, d);
        if (lane == 0) dsum[wid] = da;
        __syncthreads();
        if (t == 0) {
            double tot = 0.0;
#pragma unroll
            for (int j = 0; j < 8; j++) tot += dsum[j];
            g_w2[task] = (float)(tot * (1.0 / (double)NELEM));
        }
        __syncthreads();   // protects s_task/h reuse next iteration
    }

    // Last-block-does-finalize (single launch; graph-replay safe via reset).
    __threadfence();
    __shared__ unsigned int s_rank;
    if (t == 0) s_rank = atomicAdd(&g_done, 1u);
    __syncthreads();
    if (s_rank == GRID - 1) {
        __threadfence();  // acquire: make all g_w2 writes visible
        float sw = 0.0f;
        if (t < SL) {
            float s = 0.0f;
#pragma unroll 10
            for (int p = 0; p < NP; p++) s += g_w2[t * NP + p];
            sw = sqrtf(s * (1.0f / (float)NP));
        }
        if (t < 32) {
#pragma unroll
            for (int d = 16; d > 0; d >>= 1) sw += __shfl_down_sync(0xffffffffu, sw, d);
            if (t == 0) {
                out[0] = sw * (1.0f / (float)SL);
                g_task = 0;  // reset counters for next graph replay
                g_done = 0;
            }
        }
    }
}

extern "C" void kernel_launch(void* const* d_in, const int* in_sizes, int n_in,
                              void* d_out, int out_size) {
    // Identify projections by element count (100); the other two are the point
    // sets (W2 between order statistics is symmetric in X/Y, order irrelevant).
    const float* X = nullptr;
    const float* Y = nullptr;
    const float* PR = nullptr;
    for (int i = 0; i < n_in; i++) {
        if (in_sizes[i] == NP * 2) {
            PR = (const float*)d_in[i];
        } else if (!X) {
            X = (const float*)d_in[i];
        } else {
            Y = (const float*)d_in[i];
        }
    }
    hist_w2_kernel<<<GRID, TPB>>>(X, Y, PR, (float*)d_out);
}

// round 12
// speedup vs baseline: 1.7861x; 1.2309x over previous
#include <cuda_runtime.h>
#include <math.h>

// Problem constants (fixed shapes for this problem)
#define SL     32          // B*C slices
#define NP     50          // projections
#define NTASK  (SL * NP)   // 1600 (slice, projection) tasks
#define NELEM  32768       // samples per slice
#define NB     512         // histogram bins
#define NCOPY  32          // lane-private copies: word = bin*32 + lane (bank == lane)
#define RSCALE 32.0f       // NB / 16  (range [-8, 8])
#define BIASF  256.0f      // NB / 2
#define BINW   (1.0f/32.0f)
#define TPB    512
#define BPSM   3
#define GRID   (148 * BPSM)   // 444 blocks; ~3.6 tasks per block slot (stolen)

// Dynamic smem layout: [0, 64KB) replicated hist, then reduced CDF table.
#define H32_WORDS (NB * NCOPY)            // 16384 words = 64 KB
#define SMEM_BYTES ((H32_WORDS + NB + 1) * 4)

__device__ float g_w2[NTASK];
__device__ unsigned int g_task = 0;
__device__ unsigned int g_done = 0;

__device__ __forceinline__ int cumX(const unsigned int* h, int b) { return (int)(h[b] & 0xffffu); }
__device__ __forceinline__ int cumY(const unsigned int* h, int b) { return (int)(h[b] >> 16); }

// Float-domain bin: clamp on the fma pipe (FMNMX), single F2I at the end.
__device__ __forceinline__ int fbin(float vx, float vy, float a0, float a1) {
    float v = fmaf(vx, a0, fmaf(vy, a1, BIASF));
    v = fminf(fmaxf(v, 0.0f), (float)(NB - 1));
    return (int)v;
}

// Exclusive SIMD scan of packed (X lo16 | Y hi16) table: 1 word per thread.
// Each half's cum <= 32768 = 0x8000: lo16 never carries into hi16.
__device__ __forceinline__ void scan_packed(unsigned int* h, unsigned int* wsum, int t) {
    const unsigned int v = h[t];
    const int lane = t & 31, wid = t >> 5;   // 16 warps
    unsigned int inc = v;
#pragma unroll
    for (int d = 1; d < 32; d <<= 1) {
        unsigned int y = __shfl_up_sync(0xffffffffu, inc, d);
        if (lane >= d) inc += y;
    }
    if (lane == 31) wsum[wid] = inc;
    __syncthreads();
    if (t == 0) {
        unsigned int s2 = 0;
#pragma unroll
        for (int j = 0; j < 16; j++) { unsigned int tmp = wsum[j]; wsum[j] = s2; s2 += tmp; }
    }
    __syncthreads();
    h[t] = inc - v + wsum[wid];   // exclusive prefix
    __syncthreads();
}

// Merge step-quantile functions over this thread's rank range.
__device__ __forceinline__ float merge_ranks(const unsigned int* h, int t) {
    const int perT = NELEM / TPB;          // 64
    const int r0 = t * perT;
    const int r1 = r0 + perT;

    int bx = 0, by = 0;
#pragma unroll
    for (int step = NB / 2; step > 0; step >>= 1)
        if (cumX(h, bx + step) <= r0) bx += step;
#pragma unroll
    for (int step = NB / 2; step > 0; step >>= 1)
        if (cumY(h, by + step) <= r0) by += step;

    float acc = 0.0f;
    int r = r0;
    while (r < r1) {
        int nx = cumX(h, bx + 1);
        int ny = cumY(h, by + 1);
        int nb = min(min(nx, ny), r1);
        float d = (float)(bx - by) * BINW;
        acc += (float)(nb - r) * d * d;
        r = nb;
        if (r >= r1) break;
        while (cumX(h, bx + 1) <= r) ++bx;
        while (cumY(h, by + 1) <= r) ++by;
    }
    return acc;
}

__global__ __launch_bounds__(TPB, BPSM)
void hist_w2_kernel(const float* __restrict__ X,
                    const float* __restrict__ Y,
                    const float* __restrict__ PR,
                    float* __restrict__ out) {
    extern __shared__ unsigned int smem[];
    unsigned int* h32 = smem;                 // [NB*32] lane-private packed counts
    unsigned int* h   = smem + H32_WORDS;     // [NB+1]  reduced packed CDF

    __shared__ unsigned int wsum[16];
    __shared__ double dsum[16];
    __shared__ unsigned int s_task;

    const int t = threadIdx.x;
    const int lane = t & 31;

    for (;;) {
        // Dynamic task fetch: placement-independent load balance.
        if (t == 0) s_task = atomicAdd(&g_task, 1u);
        __syncthreads();
        const int task = (int)s_task;
        if (task >= NTASK) break;

        const int sl = task / NP;
        const int p  = task - sl * NP;

        const float a0 = PR[2 * p]     * RSCALE;
        const float a1 = PR[2 * p + 1] * RSCALE;

        // Zero the replicated table (vectorized; conflict-free streaming stores).
        {
            uint4 z = make_uint4(0u, 0u, 0u, 0u);
            uint4* h32v = (uint4*)h32;
#pragma unroll
            for (int i = t; i < H32_WORDS / 4; i += TPB) h32v[i] = z;
        }
        __syncthreads();

        const float4* xs = (const float4*)X + (size_t)sl * (NELEM / 2);
        const float4* ys = (const float4*)Y + (size_t)sl * (NELEM / 2);

        // Histogram pass: 2x unrolled -> 4 independent LDG.128 per iter (MLP=4).
        // word = bin*32 + lane  =>  bank == lane: every atomic is 1 wavefront,
        // no conflicts, no same-bin serialization.
        for (int i = t; i < NELEM / 2; i += 2 * TPB) {
            float4 xv0 = xs[i];
            float4 xv1 = xs[i + TPB];
            float4 yv0 = ys[i];
            float4 yv1 = ys[i + TPB];

            int xa = fbin(xv0.x, xv0.y, a0, a1);
            int xb = fbin(xv0.z, xv0.w, a0, a1);
            int xc = fbin(xv1.x, xv1.y, a0, a1);
            int xd = fbin(xv1.z, xv1.w, a0, a1);
            int ya = fbin(yv0.x, yv0.y, a0, a1);
            int yb = fbin(yv0.z, yv0.w, a0, a1);
            int yc = fbin(yv1.x, yv1.y, a0, a1);
            int yd = fbin(yv1.z, yv1.w, a0, a1);

            atomicAdd(&h32[(xa << 5) | lane], 1u);
            atomicAdd(&h32[(xb << 5) | lane], 1u);
            atomicAdd(&h32[(xc << 5) | lane], 1u);
            atomicAdd(&h32[(xd << 5) | lane], 1u);
            atomicAdd(&h32[(ya << 5) | lane], 0x10000u);
            atomicAdd(&h32[(yb << 5) | lane], 0x10000u);
            atomicAdd(&h32[(yc << 5) | lane], 0x10000u);
            atomicAdd(&h32[(yd << 5) | lane], 0x10000u);
        }
        __syncthreads();

        // Reduce 32 copies -> packed per-bin counts. One bin per thread;
        // lane-rotated reads keep every access conflict-free.
        // SIMD u32 add is safe: each 16-bit half total <= 32768.
        {
            const unsigned int* row = h32 + (t << 5);
            unsigned int sum = 0;
#pragma unroll
            for (int j = 0; j < 32; j++) sum += row[(lane + j) & 31];
            h[t] = sum;
        }
        __syncthreads();

        scan_packed(h, wsum, t);
        if (t == 0) h[NB] = 0x80008000u;
        __syncthreads();

        float acc = merge_ranks(h, t);

        // Block reduction in double.
        double da = (double)acc;
        const int wid = t >> 5;
#pragma unroll
        for (int d = 16; d > 0; d >>= 1) da += __shfl_down_sync(0xffffffffu, da, d);
        if (lane == 0) dsum[wid] = da;
        __syncthreads();
        if (t == 0) {
            double tot = 0.0;
#pragma unroll
            for (int j = 0; j < 16; j++) tot += dsum[j];
            g_w2[task] = (float)(tot * (1.0 / (double)NELEM));
        }
        __syncthreads();   // protects s_task/smem reuse next iteration
    }

    // Last-block-does-finalize (single launch; graph-replay safe via reset).
    __threadfence();
    __shared__ unsigned int s_rank;
    if (t == 0) s_rank = atomicAdd(&g_done, 1u);
    __syncthreads();
    if (s_rank == GRID - 1) {
        __threadfence();  // acquire: make all g_w2 writes visible
        float sw = 0.0f;
        if (t < SL) {
            float s = 0.0f;
#pragma unroll 10
            for (int p = 0; p < NP; p++) s += g_w2[t * NP + p];
            sw = sqrtf(s * (1.0f / (float)NP));
        }
        if (t < 32) {
#pragma unroll
            for (int d = 16; d > 0; d >>= 1) sw += __shfl_down_sync(0xffffffffu, sw, d);
            if (t == 0) {
                out[0] = sw * (1.0f / (float)SL);
                g_task = 0;  // reset counters for next graph replay
                g_done = 0;
            }
        }
    }
}

extern "C" void kernel_launch(void* const* d_in, const int* in_sizes, int n_in,
                              void* d_out, int out_size) {
    // Identify projections by element count (100); the other two are the point
    // sets (W2 between order statistics is symmetric in X/Y, order irrelevant).
    const float* X = nullptr;
    const float* Y = nullptr;
    const float* PR = nullptr;
    for (int i = 0; i < n_in; i++) {
        if (in_sizes[i] == NP * 2) {
            PR = (const float*)d_in[i];
        } else if (!X) {
            X = (const float*)d_in[i];
        } else {
            Y = (const float*)d_in[i];
        }
    }
    // Opt in to >48KB dynamic shared memory (host-side attribute; not a stream op).
    cudaFuncSetAttribute(hist_w2_kernel,
                         cudaFuncAttributeMaxDynamicSharedMemorySize, SMEM_BYTES);
    hist_w2_kernel<<<GRID, TPB, SMEM_BYTES>>>(X, Y, PR, (float*)d_out);
}